// round 17
// baseline (speedup 1.0000x reference)
#include <cuda_runtime.h>
#include <cuda_fp16.h>
#include <cstdint>

#define Bn 256
#define Tn 128
#define Dn 300
#define Hn 512
#define G4 2048
#define OUTD 200

typedef unsigned long long u64;

// -------- static scratch --------
__device__ float g_X[2][Tn * Bn * G4];        // layer-0 input projections
__device__ float g_H1[2][Tn * Bn * Hn];       // layer1 h row-major (final gather)
__device__ __half g_Hph[2][2][Tn][2][128 * 512];  // fp16 h images, frag order
__device__ uint2 g_W1f[2][32][8192];          // W1x fragment image (gate-interleaved)
__device__ int g_cnt4[4];
__device__ int g_gen4[4];

// -------- mma helpers --------
__device__ __forceinline__ void mma16(float* d, uint32_t a0, uint32_t a1,
                                      uint32_t a2, uint32_t a3,
                                      uint32_t b0, uint32_t b1) {
    asm volatile(
        "mma.sync.aligned.m16n8k16.row.col.f32.f16.f16.f32 "
        "{%0,%1,%2,%3}, {%4,%5,%6,%7}, {%8,%9}, {%0,%1,%2,%3};"
        : "+f"(d[0]), "+f"(d[1]), "+f"(d[2]), "+f"(d[3])
        : "r"(a0), "r"(a1), "r"(a2), "r"(a3), "r"(b0), "r"(b1));
}
__device__ __forceinline__ uint32_t smem_u32(const void* p) {
    uint32_t a;
    asm("{ .reg .u64 t; cvta.to.shared.u64 t, %1; cvt.u32.u64 %0, t; }"
        : "=r"(a) : "l"(p));
    return a;
}
__device__ __forceinline__ u64 gaddr(const void* p) {
    u64 g;
    asm("cvta.to.global.u64 %0, %1;" : "=l"(g) : "l"(p));
    return g;
}
__device__ __forceinline__ uint32_t h2bits(float lo, float hi) {
    __half2 h = __floats2half2_rn(lo, hi);
    return *reinterpret_cast<uint32_t*>(&h);
}

// -------- fast activations --------
__device__ __forceinline__ float fast_ex2(float x) {
    float y; asm("ex2.approx.f32 %0, %1;" : "=f"(y) : "f"(x)); return y;
}
__device__ __forceinline__ float fast_rcp(float x) {
    float y; asm("rcp.approx.f32 %0, %1;" : "=f"(y) : "f"(x)); return y;
}
__device__ __forceinline__ float sigf(float x) {
    return fast_rcp(1.0f + fast_ex2(-1.4426950408889634f * x));
}
__device__ __forceinline__ float tanhfast(float x) {
    return 2.0f * fast_rcp(1.0f + fast_ex2(-2.8853900817779268f * x)) - 1.0f;
}

__device__ __forceinline__ float4 gload4(const float* p, int k0, int K) {
    if (k0 + 3 < K) return *(const float4*)p;
    float4 v = make_float4(0.f, 0.f, 0.f, 0.f);
    if (k0 < K)     v.x = p[0];
    if (k0 + 1 < K) v.y = p[1];
    if (k0 + 2 < K) v.z = p[2];
    return v;
}

// ============================================================================
// W1x fragment prep: gate-interleaved col map (n = unit*4 + gate).
// ============================================================================
__global__ __launch_bounds__(256) void wprep1(
    const float* __restrict__ WL1, const float* __restrict__ WR1)
{
    const int e = blockIdx.y, s = blockIdx.x, u0 = s * 16;
    const float* Wx = e ? WR1 : WL1;
    uint2* dst = g_W1f[e][s];
    const int tid = threadIdx.x;
#pragma unroll 4
    for (int i = 0; i < 32; i++) {
        int idx = tid + 256 * i;
        int ln = idx & 31, nt = (idx >> 5) & 7, kg = idx >> 8;
        int n = nt * 8 + (ln >> 2);
        int k0 = kg * 16 + (ln & 3) * 2;
        int col = (n & 3) * 512 + u0 + (n >> 2);
        dst[idx] = make_uint2(
            h2bits(Wx[(size_t)k0 * G4 + col], Wx[(size_t)(k0 + 1) * G4 + col]),
            h2bits(Wx[(size_t)(k0 + 8) * G4 + col], Wx[(size_t)(k0 + 9) * G4 + col]));
    }
}

// ============================================================================
// Layer-0 input projection via fp16 mma.sync (embed, K=300) — unchanged.
// ============================================================================
#define XA_PITCH 48

__global__ __launch_bounds__(256) void xproj_mma(
    const float* __restrict__ AL, const float* __restrict__ AR,
    const float* __restrict__ WL, const float* __restrict__ WR,
    const float* __restrict__ bL, const float* __restrict__ bR,
    int K)
{
    __shared__ __align__(16) char Asm[128 * XA_PITCH];
    __shared__ __align__(16) char Wsm[128 * XA_PITCH];

    const int e = blockIdx.z;
    const float* A    = e ? AR : AL;
    const float* W    = e ? WR : WL;
    const float* bias = e ? bR : bL;
    float* Out = g_X[e];

    const int m0 = blockIdx.x * 128;
    const int n0 = blockIdx.y * 128;
    const int tid = threadIdx.x, lane = tid & 31, wid = tid >> 5;
    const int wm = wid & 1, wn = wid >> 1;
    const int gid = lane >> 2, tig = lane & 3;
    const int tt = m0 >> 8;

    float d[4][4][4];
#pragma unroll
    for (int a = 0; a < 4; a++)
#pragma unroll
        for (int b = 0; b < 4; b++)
#pragma unroll
            for (int c = 0; c < 4; c++) d[a][b][c] = 0.0f;

    const int arow = tid >> 1, ag = tid & 1;
    const int wg = tid >> 7, wtk = (tid >> 5) & 3, wcc = tid & 31;
    const size_t arow_off = ((size_t)((m0 & 255) + arow) * Tn + tt) * K;

    const int nk = (K + 15) >> 4;
    for (int kc16 = 0; kc16 < nk; kc16++) {
        const int kc = kc16 * 16;
        __syncthreads();
        {
            const float* ap = A + arow_off + kc + ag * 8;
            int kb = kc + ag * 8;
            float4 lo = (kb     < K) ? gload4(ap, kb, K)
                                     : make_float4(0.f, 0.f, 0.f, 0.f);
            float4 hi = (kb + 4 < K) ? gload4(ap + 4, kb + 4, K)
                                     : make_float4(0.f, 0.f, 0.f, 0.f);
            char* dst = Asm + arow * XA_PITCH + ag * 4;
            *(uint32_t*)(dst + 0)  = h2bits(lo.x, lo.y);
            *(uint32_t*)(dst + 8)  = h2bits(lo.z, lo.w);
            *(uint32_t*)(dst + 16) = h2bits(hi.x, hi.y);
            *(uint32_t*)(dst + 24) = h2bits(hi.z, hi.w);
        }
        {
            int k1 = kc + wg * 8 + wtk * 2;
            const float* wp1 = W + (size_t)k1 * G4 + n0 + wcc * 4;
            const float* wp2 = W + (size_t)(k1 + 1) * G4 + n0 + wcc * 4;
            float4 lo = (k1     < K) ? *(const float4*)wp1
                                     : make_float4(0.f, 0.f, 0.f, 0.f);
            float4 hi = (k1 + 1 < K) ? *(const float4*)wp2
                                     : make_float4(0.f, 0.f, 0.f, 0.f);
            int off = wtk * 8 + wg * 4;
            *(uint32_t*)(Wsm + (wcc * 4 + 0) * XA_PITCH + off) = h2bits(lo.x, hi.x);
            *(uint32_t*)(Wsm + (wcc * 4 + 1) * XA_PITCH + off) = h2bits(lo.y, hi.y);
            *(uint32_t*)(Wsm + (wcc * 4 + 2) * XA_PITCH + off) = h2bits(lo.z, hi.z);
            *(uint32_t*)(Wsm + (wcc * 4 + 3) * XA_PITCH + off) = h2bits(lo.w, hi.w);
        }
        __syncthreads();
        {
            uint2 bf[4];
#pragma unroll
            for (int j = 0; j < 4; j++) {
                int col = wn * 32 + j * 8 + gid;
                bf[j] = *(const uint2*)(Wsm + col * XA_PITCH + tig * 8);
            }
#pragma unroll
            for (int ms = 0; ms < 4; ms++) {
                int R = wm * 64 + ms * 16;
                uint2 alo = *(const uint2*)(Asm + (R + gid) * XA_PITCH + tig * 8);
                uint2 ahi = *(const uint2*)(Asm + (R + 8 + gid) * XA_PITCH + tig * 8);
#pragma unroll
                for (int j = 0; j < 4; j++)
                    mma16(d[ms][j], alo.x, ahi.x, alo.y, ahi.y, bf[j].x, bf[j].y);
            }
        }
    }

#pragma unroll
    for (int ms = 0; ms < 4; ms++) {
        int r = m0 + wm * 64 + ms * 16 + gid;
#pragma unroll
        for (int j = 0; j < 4; j++) {
            int n = n0 + wn * 32 + j * 8 + tig * 2;
            float2 bv = *(const float2*)&bias[n];
            *(float2*)&Out[(size_t)r * G4 + n] =
                make_float2(d[ms][j][0] + bv.x, d[ms][j][1] + bv.y);
            *(float2*)&Out[(size_t)(r + 8) * G4 + n] =
                make_float2(d[ms][j][2] + bv.x, d[ms][j][3] + bv.y);
        }
    }
}

// ============================================================================
// Fused two-layer LSTM, single pipeline per tau, gate-interleaved N, no zs.
// 128 CTAs = e(2) x m(2) x s(32); 512 thr = wm(4) x wn(4) warps, full-K.
// kc0-3: h0[tau-1] (+W1x stream) -> z0 (WB0) and z1x; epilogue-0 (shuffle,
// no syncs) overlaps kc4-5 loads; kc4-7: h1[tau-2] -> z1 += (WB1).
// ============================================================================
#define WB0_OFF   0
#define WB1_OFF   65536
#define STG_OFF   131072
#define SLOT_SZ   49152                        // 32KB h + 16KB W stream
#define SMEM_DYN  (STG_OFF + 2 * SLOT_SZ)      // 229376

__global__ __launch_bounds__(512, 1) void lstm_fused(
    const float* __restrict__ W0L, const float* __restrict__ W0R,
    const float* __restrict__ W1L, const float* __restrict__ W1R,
    const float* __restrict__ b1L, const float* __restrict__ b1R)
{
    extern __shared__ __align__(16) char sm[];
    uint2* WB0 = (uint2*)(sm + WB0_OFF);
    uint2* WB1 = (uint2*)(sm + WB1_OFF);
    const uint32_t smb = smem_u32(sm);
    const uint32_t stgb = smb + STG_OFF;

    const int tid = threadIdx.x, lane = tid & 31, wid = tid >> 5;
    const int wm = wid >> 2, wn = wid & 3;      // 4 x 4 warp grid, full K
    const int gid = lane >> 2, tig = lane & 3;
    const int e = blockIdx.x >> 6;
    const int m = (blockIdx.x >> 5) & 1;
    const int s = blockIdx.x & 31;
    const int grp = blockIdx.x >> 5;
    const int m0 = m * 128, u0 = s * 16;

    const float* W0h = (e ? W0R : W0L) + (size_t)Dn * G4;
    const float* W1h = (e ? W1R : W1L) + (size_t)Hn * G4;
    const float* B1  = e ? b1R : b1L;
    const float* X   = g_X[e];

    // ---- resident W fragments (gate-interleaved col map) ----
#pragma unroll 2
    for (int i = 0; i < 16; i++) {
        int idx = tid + 512 * i;
        int ln = idx & 31, nt = (idx >> 5) & 7, kg = idx >> 8;
        int n = nt * 8 + (ln >> 2);
        int k0 = kg * 16 + (ln & 3) * 2;
        int col = (n & 3) * 512 + u0 + (n >> 2);
        WB0[idx] = make_uint2(
            h2bits(W0h[(size_t)k0 * G4 + col], W0h[(size_t)(k0 + 1) * G4 + col]),
            h2bits(W0h[(size_t)(k0 + 8) * G4 + col], W0h[(size_t)(k0 + 9) * G4 + col]));
        WB1[idx] = make_uint2(
            h2bits(W1h[(size_t)k0 * G4 + col], W1h[(size_t)(k0 + 1) * G4 + col]),
            h2bits(W1h[(size_t)(k0 + 8) * G4 + col], W1h[(size_t)(k0 + 9) * G4 + col]));
    }

    // ---- per-thread cell geometry ----
    const int evenp = !(lane & 1);              // even -> gates i,j ; row gid
    int rr[2], ulj[2], pim[2];
    rr[0] = wm * 32 + (evenp ? gid : gid + 8);
    rr[1] = rr[0] + 16;
#pragma unroll
    for (int j = 0; j < 2; j++) {
        ulj[j] = wn * 4 + j * 2 + ((lane >> 1) & 1);
        pim[j] = s * 16 + ((ulj[j] & 7) >> 1) * 4 + ((ulj[j] >> 3) & 1) * 2 + (ulj[j] & 1);
    }
    float creg0[2][2], creg1[2][2], b1v[2][4];
#pragma unroll
    for (int a = 0; a < 2; a++)
#pragma unroll
        for (int b = 0; b < 2; b++) { creg0[a][b] = 0.f; creg1[a][b] = 0.f; }
#pragma unroll
    for (int j = 0; j < 2; j++)
#pragma unroll
        for (int g = 0; g < 4; g++)
            b1v[j][g] = B1[(g << 9) + u0 + ulj[j]];

    const int crow = tid >> 2, cb = (tid & 3) * 2;

    // ---- X prefetch for tau=0 ----
    float xg[2][2][4];
#pragma unroll
    for (int ms = 0; ms < 2; ms++)
#pragma unroll
        for (int j = 0; j < 2; j++) {
            const float* Xb = X + ((size_t)m0 + rr[ms]) * G4 + u0 + ulj[j];
#pragma unroll
            for (int g = 0; g < 4; g++) xg[ms][j][g] = Xb[g << 9];
        }

    __syncthreads();

#define ISSUE_H(hg_, kc_, dstb_) do {                                       \
    u64 srcb = (hg_) + (u64)crow * 1024 + (u64)(kc_) * 256;                 \
    uint32_t da0 = (dstb_) + crow * 256 + (((cb)     ^ (crow & 7)) << 5);   \
    uint32_t da1 = (dstb_) + crow * 256 + (((cb + 1) ^ (crow & 7)) << 5);   \
    asm volatile("cp.async.cg.shared.global [%0], [%1], 16;" :: "r"(da0), "l"(srcb + cb * 32)); \
    asm volatile("cp.async.cg.shared.global [%0], [%1], 16;" :: "r"(da0 + 16), "l"(srcb + cb * 32 + 16)); \
    asm volatile("cp.async.cg.shared.global [%0], [%1], 16;" :: "r"(da1), "l"(srcb + cb * 32 + 32)); \
    asm volatile("cp.async.cg.shared.global [%0], [%1], 16;" :: "r"(da1 + 16), "l"(srcb + cb * 32 + 48)); \
} while (0)
#define ISSUE_W(wg_, kc_, dstb_) do {                                       \
    u64 srcw = (wg_) + (u64)(kc_) * 16384 + (u64)tid * 32;                  \
    uint32_t dw = (dstb_) + tid * 32;                                       \
    asm volatile("cp.async.cg.shared.global [%0], [%1], 16;" :: "r"(dw), "l"(srcw)); \
    asm volatile("cp.async.cg.shared.global [%0], [%1], 16;" :: "r"(dw + 16), "l"(srcw + 16)); \
} while (0)
#define COMMIT() asm volatile("cp.async.commit_group;")

    for (int tau = 0; tau <= Tn; tau++) {
        float d0[2][2][4], d1[2][2][4];
#pragma unroll
        for (int a = 0; a < 2; a++)
#pragma unroll
            for (int b = 0; b < 2; b++)
#pragma unroll
                for (int c = 0; c < 4; c++) { d0[a][b][c] = 0.f; d1[a][b][c] = 0.f; }

        const int do_z0 = (tau >= 1) && (tau < Tn);
        const int nchunks = (tau >= 2) ? 8 : ((tau >= 1) ? 4 : 0);
        const u64 hg0 = (tau >= 1) ? gaddr(&g_Hph[0][e][tau - 1][m][0]) : 0;
        const u64 hg1 = (tau >= 2) ? gaddr(&g_Hph[1][e][tau - 2][m][0]) : 0;
        const u64 wg1 = gaddr(&g_W1f[e][s][0]);

        if (nchunks) {
            ISSUE_H(hg0, 0, stgb); ISSUE_W(wg1, 0, stgb + 32768); COMMIT();
            ISSUE_H(hg0, 1, stgb + SLOT_SZ); ISSUE_W(wg1, 1, stgb + SLOT_SZ + 32768); COMMIT();
        }

        for (int kc = 0; kc < nchunks; kc++) {
            if (kc < nchunks - 1)
                asm volatile("cp.async.wait_group 1;" ::: "memory");
            else
                asm volatile("cp.async.wait_group 0;" ::: "memory");
            __syncthreads();
            const char* stg = sm + STG_OFF + (kc & 1) * SLOT_SZ;
            if (kc < 4) {
                const uint2* wz1 = (const uint2*)(stg + 32768);
                const uint2* wz0 = WB0 + (size_t)kc * 2048;
#pragma unroll
                for (int gl = 0; gl < 8; gl++) {
                    uint2 a_[2][2];
#pragma unroll
                    for (int ms = 0; ms < 2; ms++) {
                        int rlo = wm * 32 + ms * 16 + gid, rhi = rlo + 8;
                        a_[ms][0] = *(const uint2*)(stg + rlo * 256 +
                                        ((gl ^ (rlo & 7)) << 5) + tig * 8);
                        a_[ms][1] = *(const uint2*)(stg + rhi * 256 +
                                        ((gl ^ (rhi & 7)) << 5) + tig * 8);
                    }
#pragma unroll
                    for (int j = 0; j < 2; j++) {
                        int nt = wn * 2 + j;
                        uint2 b1f = wz1[((size_t)gl * 8 + nt) * 32 + lane];
#pragma unroll
                        for (int ms = 0; ms < 2; ms++)
                            mma16(d1[ms][j], a_[ms][0].x, a_[ms][1].x,
                                  a_[ms][0].y, a_[ms][1].y, b1f.x, b1f.y);
                        if (do_z0) {
                            uint2 b0f = wz0[((size_t)gl * 8 + nt) * 32 + lane];
#pragma unroll
                            for (int ms = 0; ms < 2; ms++)
                                mma16(d0[ms][j], a_[ms][0].x, a_[ms][1].x,
                                      a_[ms][0].y, a_[ms][1].y, b0f.x, b0f.y);
                        }
                    }
                }
            } else {
                const uint2* wz = WB1 + (size_t)(kc - 4) * 2048;
#pragma unroll
                for (int gl = 0; gl < 8; gl++) {
                    uint2 a_[2][2];
#pragma unroll
                    for (int ms = 0; ms < 2; ms++) {
                        int rlo = wm * 32 + ms * 16 + gid, rhi = rlo + 8;
                        a_[ms][0] = *(const uint2*)(stg + rlo * 256 +
                                        ((gl ^ (rlo & 7)) << 5) + tig * 8);
                        a_[ms][1] = *(const uint2*)(stg + rhi * 256 +
                                        ((gl ^ (rhi & 7)) << 5) + tig * 8);
                    }
#pragma unroll
                    for (int j = 0; j < 2; j++) {
                        int nt = wn * 2 + j;
                        uint2 bf = wz[((size_t)gl * 8 + nt) * 32 + lane];
#pragma unroll
                        for (int ms = 0; ms < 2; ms++)
                            mma16(d1[ms][j], a_[ms][0].x, a_[ms][1].x,
                                  a_[ms][0].y, a_[ms][1].y, bf.x, bf.y);
                    }
                }
            }
            if (kc + 2 < nchunks) {
                __syncthreads();
                int kcn = kc + 2;
                uint32_t db = stgb + (kcn & 1) * SLOT_SZ;
                if (kcn < 4) {
                    ISSUE_H(hg0, kcn, db); ISSUE_W(wg1, kcn, db + 32768);
                } else {
                    ISSUE_H(hg1, kcn - 4, db);
                }
                COMMIT();
            }
            // ---- epilogue-0 after z0 complete (overlaps kc4-5 loads) ----
            if (kc == 3 && tau < Tn) {
                __half* hw = &g_Hph[0][e][tau][m][0];
#pragma unroll
                for (int ms = 0; ms < 2; ms++)
#pragma unroll
                    for (int j = 0; j < 2; j++) {
                        float* dd = d0[ms][j];
                        float s0 = evenp ? dd[2] : dd[0];
                        float s1 = evenp ? dd[3] : dd[1];
                        float r0 = __shfl_xor_sync(0xffffffffu, s0, 1);
                        float r1 = __shfl_xor_sync(0xffffffffu, s1, 1);
                        float zi = xg[ms][j][0] + (evenp ? dd[0] : r0);
                        float zj = xg[ms][j][1] + (evenp ? dd[1] : r1);
                        float zf = xg[ms][j][2] + (evenp ? r0 : dd[2]);
                        float zo = xg[ms][j][3] + (evenp ? r1 : dd[3]);
                        float cn = creg0[ms][j] * sigf(zf + 1.0f) +
                                   sigf(zi) * tanhfast(zj);
                        creg0[ms][j] = cn;
                        hw[rr[ms] * 512 + pim[j]] =
                            __float2half_rn(tanhfast(cn) * sigf(zo));
                    }
            }
        }

        // tau == 0: epilogue-0 with z = X only
        if (tau == 0) {
            __half* hw = &g_Hph[0][e][0][m][0];
#pragma unroll
            for (int ms = 0; ms < 2; ms++)
#pragma unroll
                for (int j = 0; j < 2; j++) {
                    float zi = xg[ms][j][0], zj = xg[ms][j][1];
                    float zf = xg[ms][j][2], zo = xg[ms][j][3];
                    float cn = sigf(zf + 1.0f) * 0.0f + sigf(zi) * tanhfast(zj);
                    creg0[ms][j] = cn;
                    hw[rr[ms] * 512 + pim[j]] =
                        __float2half_rn(tanhfast(cn) * sigf(zo));
                }
        }

        // ---- epilogue-1 (L1 step tau-1): pure register/shuffle ----
        if (tau >= 1) {
            __half* hw = &g_Hph[1][e][tau - 1][m][0];
            float* hr = g_H1[e] + ((size_t)(tau - 1) * Bn + m0) * Hn + u0;
#pragma unroll
            for (int ms = 0; ms < 2; ms++)
#pragma unroll
                for (int j = 0; j < 2; j++) {
                    float* dd = d1[ms][j];
                    float s0 = evenp ? dd[2] : dd[0];
                    float s1 = evenp ? dd[3] : dd[1];
                    float r0 = __shfl_xor_sync(0xffffffffu, s0, 1);
                    float r1 = __shfl_xor_sync(0xffffffffu, s1, 1);
                    float zi = b1v[j][0] + (evenp ? dd[0] : r0);
                    float zj = b1v[j][1] + (evenp ? dd[1] : r1);
                    float zf = b1v[j][2] + (evenp ? r0 : dd[2]);
                    float zo = b1v[j][3] + (evenp ? r1 : dd[3]);
                    float cn = creg1[ms][j] * sigf(zf + 1.0f) +
                               sigf(zi) * tanhfast(zj);
                    creg1[ms][j] = cn;
                    float hv = tanhfast(cn) * sigf(zo);
                    hr[(size_t)rr[ms] * Hn + ulj[j]] = hv;
                    hw[rr[ms] * 512 + pim[j]] = __float2half_rn(hv);
                }
        }

        // ---- X prefetch + group barrier ----
        if (tau < Tn) {
            if (tau < Tn - 1) {
#pragma unroll
                for (int ms = 0; ms < 2; ms++)
#pragma unroll
                    for (int j = 0; j < 2; j++) {
                        const float* Xb = X + ((size_t)(tau + 1) * Bn + m0 + rr[ms]) * G4
                                          + u0 + ulj[j];
#pragma unroll
                        for (int g = 0; g < 4; g++) xg[ms][j][g] = Xb[g << 9];
                    }
            }
            __threadfence();
            __syncthreads();
            if (tid == 0) {
                int g = *((volatile int*)&g_gen4[grp]);
                if (atomicAdd(&g_cnt4[grp], 1) == 31) {
                    g_cnt4[grp] = 0;
                    __threadfence();
                    atomicAdd(&g_gen4[grp], 1);
                } else {
                    while (*((volatile int*)&g_gen4[grp]) == g) { }
                }
            }
            __syncthreads();
        }
    }
#undef ISSUE_H
#undef ISSUE_W
#undef COMMIT
}

// ============================================================================
// Gather + final projection: 128 CTAs x 2 rows, 1024 thr, 4-way k-split.
// ============================================================================
__global__ __launch_bounds__(1024) void final_kernel(
    const int* __restrict__ lenL, const int* __restrict__ lenR,
    const float* __restrict__ Wt, float* __restrict__ out)
{
    __shared__ float v[2][1024];
    __shared__ float part[3][2][OUTD];
    const int tid = threadIdx.x;
    const int o = tid & 255, ks = tid >> 8;
    const int b0 = blockIdx.x * 2;
#pragma unroll
    for (int r = 0; r < 2; r++) {
        int b = b0 + r;
        int iL = lenL[b] - 1, iR = lenR[b] - 1;
        if (tid < 512)
            v[r][tid] = g_H1[0][((size_t)iL * Bn + b) * Hn + tid];
        else
            v[r][tid] = g_H1[1][((size_t)iR * Bn + b) * Hn + tid - 512];
    }
    __syncthreads();
    float acc0 = 0.f, acc1 = 0.f;
    if (o < OUTD) {
        const int k0 = ks * 256;
#pragma unroll 8
        for (int k = 0; k < 256; k++) {
            float w = Wt[(size_t)(k0 + k) * OUTD + o];
            acc0 += v[0][k0 + k] * w;
            acc1 += v[1][k0 + k] * w;
        }
        if (ks > 0) {
            part[ks - 1][0][o] = acc0;
            part[ks - 1][1][o] = acc1;
        }
    }
    __syncthreads();
    if (ks == 0 && o < OUTD) {
        out[(b0 + 0) * OUTD + o] = acc0 + part[0][0][o] + part[1][0][o] + part[2][0][o];
        out[(b0 + 1) * OUTD + o] = acc1 + part[0][1][o] + part[1][1][o] + part[2][1][o];
    }
}

// ============================================================================
extern "C" void kernel_launch(void* const* d_in, const int* in_sizes, int n_in,
                              void* d_out, int out_size)
{
    const float* left  = (const float*)d_in[0];
    const float* right = (const float*)d_in[1];
    const int*   lenL  = (const int*)d_in[2];
    const int*   lenR  = (const int*)d_in[3];
    const float* lW0 = (const float*)d_in[4];
    const float* lb0 = (const float*)d_in[5];
    const float* lW1 = (const float*)d_in[6];
    const float* lb1 = (const float*)d_in[7];
    const float* rW0 = (const float*)d_in[8];
    const float* rb0 = (const float*)d_in[9];
    const float* rW1 = (const float*)d_in[10];
    const float* rb1 = (const float*)d_in[11];
    const float* tW  = (const float*)d_in[12];
    float* out = (float*)d_out;

    static int smem_set = 0;
    if (!smem_set) {
        cudaFuncSetAttribute(lstm_fused,
                             cudaFuncAttributeMaxDynamicSharedMemorySize, SMEM_DYN);
        smem_set = 1;
    }

    dim3 gx(256, 16, 2);
    dim3 gw(32, 2);

    wprep1<<<gw, 256>>>(lW1, rW1);
    xproj_mma<<<gx, 256>>>(left, right, lW0, rW0, lb0, rb0, Dn);
    lstm_fused<<<128, 512, SMEM_DYN>>>(lW0, rW0, lW1, rW1, lb1, rb1);
    final_kernel<<<128, 1024>>>(lenL, lenR, tW, out);
}